// round 12
// baseline (speedup 1.0000x reference)
#include <cuda_runtime.h>
#include <cuda_bf16.h>
#include <math.h>
#include <stdint.h>

#define BATCH 2
#define TSEQ  1024
#define DIM   1024
#define NH    16
#define HD    64
#define NL    6
#define VOCAB 32000

// GEMM tiling (mma.sync path — portable to compute_103 virtual arch)
#define BM 128
#define BN 128
#define BK 64
#define PITCH_A     144                   // A smem row: 64 halfs + pad
#define A_BYTES     (128 * PITCH_A)       // 18432
#define PITCH_BB    272                   // B smem row: 128 halfs + pad ([k][n] layout)
#define B_BYTES     (64 * PITCH_BB)       // 17408
#define STAGE_BYTES (2 * A_BYTES + 2 * B_BYTES)   // 71680
#define GEMM_STAGES 3
#define GEMM_SMEM   (GEMM_STAGES * STAGE_BYTES)   // 215040

// attention tiling: BQ=128 queries, 64-key tiles
#define AT_PITCH 144                       // bytes per 64-half row
#define AT_TILE  (64 * AT_PITCH)           // 9216 B  (K/V tiles)
#define QT_TILE  (128 * AT_PITCH)          // 18432 B (Q tiles)
#define ATTN_SMEM (2 * QT_TILE + 4 * AT_TILE)   // 73728 B -> 2 CTAs/SM (512 thr)

// head split
#define DSPLIT 4

// ---------------- scratch (device globals; no allocation allowed) ----------
__device__ float g_h   [BATCH * TSEQ * DIM];
__device__ float g_qkv [BATCH * TSEQ * 3 * DIM];
__device__ float g_hl  [BATCH * DIM];
__device__ float g_part[DSPLIT * BATCH * VOCAB];

__device__ __nv_bfloat16 g_xh[BATCH * TSEQ * DIM];
__device__ __nv_bfloat16 g_xl[BATCH * TSEQ * DIM];
__device__ __nv_bfloat16 g_ah[BATCH * TSEQ * DIM];
__device__ __nv_bfloat16 g_al[BATCH * TSEQ * DIM];

// weights split to bf16 hi/lo, kept in ORIGINAL (L, K, N) layout
__device__ __nv_bfloat16 g_wqh[NL * DIM * 3 * DIM];
__device__ __nv_bfloat16 g_wql[NL * DIM * 3 * DIM];
__device__ __nv_bfloat16 g_woh[NL * DIM * DIM];
__device__ __nv_bfloat16 g_wol[NL * DIM * DIM];

// ==================== helpers ====================
__device__ __forceinline__ uint32_t smem_u32(const void* p) {
    uint32_t a;
    asm("{ .reg .u64 t; cvta.to.shared.u64 t, %1; cvt.u32.u64 %0, t; }" : "=r"(a) : "l"(p));
    return a;
}
__device__ __forceinline__ void cp16(uint32_t d, const void* g) {
    asm volatile("cp.async.cg.shared.global [%0], [%1], 16;" :: "r"(d), "l"(g));
}
__device__ __forceinline__ void cp_commit() {
    asm volatile("cp.async.commit_group;");
}
__device__ __forceinline__ void ldm4(uint32_t* r, uint32_t addr) {
    asm volatile("ldmatrix.sync.aligned.m8n8.x4.shared.b16 {%0,%1,%2,%3}, [%4];"
        : "=r"(r[0]), "=r"(r[1]), "=r"(r[2]), "=r"(r[3]) : "r"(addr));
}
__device__ __forceinline__ void ldm4t(uint32_t* r, uint32_t addr) {
    asm volatile("ldmatrix.sync.aligned.m8n8.x4.trans.shared.b16 {%0,%1,%2,%3}, [%4];"
        : "=r"(r[0]), "=r"(r[1]), "=r"(r[2]), "=r"(r[3]) : "r"(addr));
}
__device__ __forceinline__ void mma16816(float* c, const uint32_t* a, const uint32_t* b) {
    asm volatile("mma.sync.aligned.m16n8k16.row.col.f32.bf16.bf16.f32 "
        "{%0,%1,%2,%3}, {%4,%5,%6,%7}, {%8,%9}, {%0,%1,%2,%3};"
        : "+f"(c[0]), "+f"(c[1]), "+f"(c[2]), "+f"(c[3])
        : "r"(a[0]), "r"(a[1]), "r"(a[2]), "r"(a[3]), "r"(b[0]), "r"(b[1]));
}
__device__ __forceinline__ uint32_t packbf(float lo, float hi) {
    uint32_t r;
    asm("cvt.rn.bf16x2.f32 %0, %1, %2;" : "=r"(r) : "f"(hi), "f"(lo));
    return r;
}
// pack (a,b) into hi-word pair + residual lo-word pair (a = element 0 = low half)
__device__ __forceinline__ void split_pair(float a, float b, uint32_t& hi, uint32_t& lo) {
    float ha = __bfloat162float(__float2bfloat16(a));
    float hb = __bfloat162float(__float2bfloat16(b));
    hi = packbf(a, b);
    lo = packbf(a - ha, b - hb);
}
__device__ __forceinline__ void split_bf16(float v, __nv_bfloat16& h, __nv_bfloat16& l) {
    h = __float2bfloat16(v);
    l = __float2bfloat16(v - __bfloat162float(h));
}

// ---------------- embedding ------------------------------------------------
__global__ void embed_kernel(const int* __restrict__ tokens,
                             const float* __restrict__ te,
                             const float* __restrict__ pe,
                             float* __restrict__ h) {
    int m = blockIdx.x;
    int t = m & (TSEQ - 1);
    int tok = tokens[m];
    for (int d = threadIdx.x; d < DIM; d += 256)
        h[(size_t)m * DIM + d] = te[(size_t)tok * DIM + d] + pe[(size_t)t * DIM + d];
}

// ---------------- streaming fp32->bf16 split (no transpose) ----------------
__global__ void wsplit_kernel(const float* __restrict__ W,
                              __nv_bfloat16* __restrict__ Th,
                              __nv_bfloat16* __restrict__ Tl,
                              size_t n) {
    size_t i = ((size_t)blockIdx.x * blockDim.x + threadIdx.x) * 4;
    size_t stride = (size_t)gridDim.x * blockDim.x * 4;
    for (; i < n; i += stride) {
        float4 v = *(const float4*)(W + i);
        uint32_t h0, l0, h1, l1;
        split_pair(v.x, v.y, h0, l0);
        split_pair(v.z, v.w, h1, l1);
        *(uint2*)(Th + i) = make_uint2(h0, h1);
        *(uint2*)(Tl + i) = make_uint2(l0, l1);
    }
}

// ---------------- block reduce ---------------------------------------------
__device__ __forceinline__ float block_reduce_sum(float v, float* red) {
    #pragma unroll
    for (int o = 16; o > 0; o >>= 1) v += __shfl_down_sync(0xffffffffu, v, o);
    int w = threadIdx.x >> 5;
    if ((threadIdx.x & 31) == 0) red[w] = v;
    __syncthreads();
    if (threadIdx.x == 0) {
        float s = 0.f;
        #pragma unroll
        for (int i = 0; i < 8; i++) s += red[i];
        red[8] = s;
    }
    __syncthreads();
    float r = red[8];
    __syncthreads();
    return r;
}

// ---------------- layernorm -> split bf16 ----------------------------------
__global__ void ln_split_kernel(const float* __restrict__ src,
                                const float* __restrict__ w,
                                const float* __restrict__ bvec,
                                __nv_bfloat16* __restrict__ xh,
                                __nv_bfloat16* __restrict__ xl) {
    __shared__ float red[9];
    const int rowi = blockIdx.x;
    const float* x = src + (size_t)rowi * DIM;
    float v[4];
    #pragma unroll
    for (int i = 0; i < 4; i++) v[i] = x[threadIdx.x + i * 256];
    float mean = block_reduce_sum(v[0] + v[1] + v[2] + v[3], red) * (1.f / DIM);
    float d2 = 0.f;
    #pragma unroll
    for (int i = 0; i < 4; i++) { float t = v[i] - mean; d2 += t * t; }
    float var = block_reduce_sum(d2, red) * (1.f / DIM);
    float inv = rsqrtf(var + 1e-5f);
    #pragma unroll
    for (int i = 0; i < 4; i++) {
        int d = threadIdx.x + i * 256;
        float y = (v[i] - mean) * inv * w[d] + bvec[d];
        __nv_bfloat16 hh, ll;
        split_bf16(y, hh, ll);
        xh[(size_t)rowi * DIM + d] = hh;
        xl[(size_t)rowi * DIM + d] = ll;
    }
}

// final layernorm, only last token, fp32 out
__global__ void lnf_kernel(const float* __restrict__ src,
                           const float* __restrict__ w,
                           const float* __restrict__ bvec,
                           float* __restrict__ dst) {
    __shared__ float red[9];
    const int rowi = blockIdx.x * TSEQ + (TSEQ - 1);
    const float* x = src + (size_t)rowi * DIM;
    float v[4];
    #pragma unroll
    for (int i = 0; i < 4; i++) v[i] = x[threadIdx.x + i * 256];
    float mean = block_reduce_sum(v[0] + v[1] + v[2] + v[3], red) * (1.f / DIM);
    float d2 = 0.f;
    #pragma unroll
    for (int i = 0; i < 4; i++) { float t = v[i] - mean; d2 += t * t; }
    float var = block_reduce_sum(d2, red) * (1.f / DIM);
    float inv = rsqrtf(var + 1e-5f);
    #pragma unroll
    for (int i = 0; i < 4; i++) {
        int d = threadIdx.x + i * 256;
        dst[(size_t)blockIdx.x * DIM + d] = (v[i] - mean) * inv * w[d] + bvec[d];
    }
}

// ---------------- HMMA split-bf16 GEMM (B in native [K,N] layout) ----------
// SKIPQ: last-layer QKV — skip Q-column tiles except M-tiles holding last tokens.
template <bool RESID, bool SKIPQ>
__global__ __launch_bounds__(256, 1)
void mma_gemm(const __nv_bfloat16* __restrict__ Ah, const __nv_bfloat16* __restrict__ Al,
              const __nv_bfloat16* __restrict__ Bh, const __nv_bfloat16* __restrict__ Bl,
              const float* __restrict__ bias, float* __restrict__ C,
              int M, int N) {
    const int row0 = blockIdx.y * BM;
    const int col0 = blockIdx.x * BN;
    if (SKIPQ && col0 < DIM && (blockIdx.y & 7) != 7) return;

    extern __shared__ char smem[];
    const uint32_t sbase = smem_u32(smem);
    const int tid  = threadIdx.x;
    const int lane = tid & 31;
    const int wid  = tid >> 5;
    const int wm   = wid >> 1;
    const int wn   = wid & 1;
    const int K    = DIM;
    const int NC   = K / BK;              // 16

    float acc[2][8][4];
    #pragma unroll
    for (int i = 0; i < 2; i++)
        #pragma unroll
        for (int j = 0; j < 8; j++)
            #pragma unroll
            for (int q = 0; q < 4; q++) acc[i][j][q] = 0.f;

    auto load_stage = [&](int s, int c) {
        const uint32_t sb = sbase + s * STAGE_BYTES;
        const int kt = c * BK;
        // A: 128 rows x 64 halfs
        #pragma unroll
        for (int it = 0; it < 4; it++) {
            int lin = tid + it * 256;
            int r  = lin >> 3;
            int cq = lin & 7;
            size_t go = (size_t)(row0 + r) * K + kt + cq * 8;
            uint32_t d = sb + r * PITCH_A + cq * 16;
            cp16(d, Ah + go);
            cp16(d + A_BYTES, Al + go);
        }
        // B: 64 k-rows x 128 n-cols (native layout, contiguous rows)
        #pragma unroll
        for (int it = 0; it < 4; it++) {
            int lin = tid + it * 256;
            int r  = lin >> 4;            // 0..63 (k)
            int cq = lin & 15;            // 0..15 (n octet)
            size_t go = (size_t)(kt + r) * N + col0 + cq * 8;
            uint32_t d = sb + 2 * A_BYTES + r * PITCH_BB + cq * 16;
            cp16(d, Bh + go);
            cp16(d + B_BYTES, Bl + go);
        }
    };

    load_stage(0, 0); cp_commit();
    load_stage(1, 1); cp_commit();
    load_stage(2, 2); cp_commit();

    const int arow  = wm * 32 + (lane & 15);
    const int acol8 = (lane >> 4) << 3;
    // B via ldmatrix.trans ([k][n] storage) — attention-PV-verified mapping
    const int krow_b = (lane & 7) + ((lane >> 3) & 1) * 8;
    const int ncol_b = (lane >> 4) << 3;

    int stage = 0;
    for (int c = 0; c < NC; c++) {
        if (c + 3 <= NC)      asm volatile("cp.async.wait_group 2;");
        else if (c + 2 == NC) asm volatile("cp.async.wait_group 1;");
        else                  asm volatile("cp.async.wait_group 0;");
        __syncthreads();

        const uint32_t ab = sbase + stage * STAGE_BYTES;
        const uint32_t bb = ab + 2 * A_BYTES;
        #pragma unroll
        for (int ks = 0; ks < 4; ks++) {
            const int kc = ks * 16;
            uint32_t ah[2][4], al[2][4];
            #pragma unroll
            for (int mt = 0; mt < 2; mt++) {
                uint32_t ad = ab + (uint32_t)(arow + mt * 16) * PITCH_A + (uint32_t)(kc + acol8) * 2;
                ldm4(ah[mt], ad);
                ldm4(al[mt], ad + A_BYTES);
            }
            uint32_t bh[8][2], bl[8][2];
            #pragma unroll
            for (int ng = 0; ng < 4; ng++) {
                uint32_t bd = bb + (uint32_t)(kc + krow_b) * PITCH_BB
                                 + (uint32_t)(wn * 64 + ng * 16 + ncol_b) * 2;
                uint32_t t4[4];
                ldm4t(t4, bd);
                bh[ng * 2][0] = t4[0]; bh[ng * 2][1] = t4[1];
                bh[ng * 2 + 1][0] = t4[2]; bh[ng * 2 + 1][1] = t4[3];
                ldm4t(t4, bd + B_BYTES);
                bl[ng * 2][0] = t4[0]; bl[ng * 2][1] = t4[1];
                bl[ng * 2 + 1][0] = t4[2]; bl[ng * 2 + 1][1] = t4[3];
            }
            #pragma unroll
            for (int mt = 0; mt < 2; mt++)
                #pragma unroll
                for (int nt = 0; nt < 8; nt++) {
                    mma16816(acc[mt][nt], ah[mt], bh[nt]);
                    mma16816(acc[mt][nt], ah[mt], bl[nt]);
                    mma16816(acc[mt][nt], al[mt], bh[nt]);
                }
        }
        __syncthreads();
        if (c + 3 < NC) { load_stage(stage, c + 3); cp_commit(); }
        stage = (stage == 2) ? 0 : stage + 1;
    }

    #pragma unroll
    for (int mt = 0; mt < 2; mt++) {
        #pragma unroll
        for (int nt = 0; nt < 8; nt++) {
            int r  = row0 + wm * 32 + mt * 16 + (lane >> 2);
            int cc = col0 + wn * 64 + nt * 8 + (lane & 3) * 2;
            float b0 = bias[cc], b1 = bias[cc + 1];
            float2* p0 = (float2*)&C[(size_t)r * N + cc];
            float2* p1 = (float2*)&C[(size_t)(r + 8) * N + cc];
            float2 v0 = make_float2(acc[mt][nt][0] + b0, acc[mt][nt][1] + b1);
            float2 v1 = make_float2(acc[mt][nt][2] + b0, acc[mt][nt][3] + b1);
            if (RESID) {
                float2 o0 = *p0, o1 = *p1;
                v0.x += o0.x; v0.y += o0.y;
                v1.x += o1.x; v1.y += o1.y;
            }
            *p0 = v0;
            *p1 = v1;
        }
    }
}

// ---------------- HMMA causal flash attention (BQ=128, 256 threads) --------
// 8 warps, each owns 16 query rows. K/V in 64-key tiles; kb in [0, 2*qb+1].
// qb = qb0 - blockIdx.x (descending; heavy blocks first).
__global__ __launch_bounds__(256)
void attn_mma_kernel(const float* __restrict__ qkv,
                     __nv_bfloat16* __restrict__ oh,
                     __nv_bfloat16* __restrict__ ol,
                     int qb0) {
    extern __shared__ char asmem[];
    const uint32_t sb = smem_u32(asmem);
    const uint32_t sQh = sb;
    const uint32_t sKh = sb + 2 * QT_TILE;
    const uint32_t sVh = sKh + 2 * AT_TILE;
    const int tid = threadIdx.x, lane = tid & 31, w = tid >> 5;
    const int qb = qb0 - (int)blockIdx.x;
    const int hh = blockIdx.y, b = blockIdx.z;

    // ---- load Q tile (128 rows), fold 1/8 scale, split to bf16 hi/lo ----
    #pragma unroll
    for (int i = 0; i < 8; i++) {
        int lin = tid + i * 256, r = lin >> 4, c4 = lin & 15;
        float4 q = *(const float4*)&qkv[(size_t)(b * TSEQ + qb * 128 + r) * (3 * DIM) + hh * HD + c4 * 4];
        q.x *= 0.125f; q.y *= 0.125f; q.z *= 0.125f; q.w *= 0.125f;
        uint32_t h0, l0, h1, l1;
        split_pair(q.x, q.y, h0, l0);
        split_pair(q.z, q.w, h1, l1);
        int off = r * AT_PITCH + c4 * 8;
        *(uint2*)(asmem + off)           = make_uint2(h0, h1);
        *(uint2*)(asmem + QT_TILE + off) = make_uint2(l0, l1);
    }
    __syncthreads();

    // ---- Q fragments (loop-invariant; warp w covers rows w*16..w*16+15) ----
    uint32_t qh[4][4], ql[4][4];
    {
        int r  = (w << 4) + (lane & 15);
        int c8 = (lane >> 4) << 3;
        #pragma unroll
        for (int kc = 0; kc < 4; kc++) {
            uint32_t ad = sQh + (uint32_t)r * AT_PITCH + (uint32_t)(kc * 16 + c8) * 2;
            ldm4(qh[kc], ad);
            ldm4(ql[kc], ad + QT_TILE);
        }
    }

    float o[8][4];
    #pragma unroll
    for (int nt = 0; nt < 8; nt++)
        #pragma unroll
        for (int q = 0; q < 4; q++) o[nt][q] = 0.f;
    float mrow[2] = {-1e30f, -1e30f};
    float lrow[2] = {0.f, 0.f};

    const uint32_t krow_s = (uint32_t)((lane & 7) + ((lane >> 4) << 3));
    const uint32_t kcol_s = (uint32_t)(((lane >> 3) & 1) << 3);
    const uint32_t krow_v = (uint32_t)((lane & 7) + (((lane >> 3) & 1) << 3));
    const uint32_t ncol_v = (uint32_t)((lane >> 4) << 3);

    const int NKB = 2 * qb + 1;
    for (int kb = 0; kb <= NKB; kb++) {
        __syncthreads();   // previous iteration's K/V reads complete
        #pragma unroll
        for (int i = 0; i < 4; i++) {
            int lin = tid + i * 256, r = lin >> 4, c4 = lin & 15;
            size_t gb = (size_t)(b * TSEQ + kb * 64 + r) * (3 * DIM) + DIM + hh * HD + c4 * 4;
            float4 kv = *(const float4*)&qkv[gb];
            float4 vv = *(const float4*)&qkv[gb + DIM];
            uint32_t h0, l0, h1, l1;
            int off = r * AT_PITCH + c4 * 8;
            split_pair(kv.x, kv.y, h0, l0);
            split_pair(kv.z, kv.w, h1, l1);
            *(uint2*)(asmem + 2 * QT_TILE + off)             = make_uint2(h0, h1);
            *(uint2*)(asmem + 2 * QT_TILE + AT_TILE + off)   = make_uint2(l0, l1);
            split_pair(vv.x, vv.y, h0, l0);
            split_pair(vv.z, vv.w, h1, l1);
            *(uint2*)(asmem + 2 * QT_TILE + 2 * AT_TILE + off) = make_uint2(h0, h1);
            *(uint2*)(asmem + 2 * QT_TILE + 3 * AT_TILE + off) = make_uint2(l0, l1);
        }
        __syncthreads();

        // ---- S = Q K^T ----
        float s[8][4];
        #pragma unroll
        for (int nt = 0; nt < 8; nt++)
            #pragma unroll
            for (int q = 0; q < 4; q++) s[nt][q] = 0.f;
        #pragma unroll
        for (int kc = 0; kc < 4; kc++) {
            #pragma unroll
            for (int ng = 0; ng < 4; ng++) {
                uint32_t th[4], tl[4];
                uint32_t ad = sKh + (ng * 16 + krow_s) * AT_PITCH + (kc * 16 + kcol_s) * 2;
                ldm4(th, ad);
                ldm4(tl, ad + AT_TILE);
                mma16816(s[2 * ng],     qh[kc], th);
                mma16816(s[2 * ng],     ql[kc], th);
                mma16816(s[2 * ng],     qh[kc], tl);
                mma16816(s[2 * ng + 1], qh[kc], th + 2);
                mma16816(s[2 * ng + 1], ql[kc], th + 2);
                mma16816(s[2 * ng + 1], qh[kc], tl + 2);
            }
        }

        // ---- causal mask (global coordinates; only last two key tiles) ----
        if (kb >= 2 * qb) {
            int rg = qb * 128 + (w << 4) + (lane >> 2);   // global query row (lower)
            int cb = kb * 64;
            #pragma unroll
            for (int nt = 0; nt < 8; nt++) {
                int cg = cb + nt * 8 + (lane & 3) * 2;    // global key col
                if (cg     > rg)     s[nt][0] = -1e30f;
                if (cg + 1 > rg)     s[nt][1] = -1e30f;
                if (cg     > rg + 8) s[nt][2] = -1e30f;
                if (cg + 1 > rg + 8) s[nt][3] = -1e30f;
            }
        }

        // ---- online softmax (two rows per thread) ----
        #pragma unroll
        for (int hf = 0; hf < 2; hf++) {
            float mx = -1e30f;
            #pragma unroll
            for (int nt = 0; nt < 8; nt++)
                mx = fmaxf(mx, fmaxf(s[nt][2 * hf], s[nt][2 * hf + 1]));
            mx = fmaxf(mx, __shfl_xor_sync(0xffffffffu, mx, 1));
            mx = fmaxf(mx, __shfl_xor_sync(0xffffffffu, mx, 2));
            float mnew  = fmaxf(mrow[hf], mx);
            float alpha = __expf(mrow[hf] - mnew);
            mrow[hf] = mnew;
            float sum = 0.f;
            #pragma unroll
            for (int nt = 0; nt < 8; nt++) {
                float p0 = __expf(s[nt][2 * hf]     - mnew);
                float p1 = __expf(s[nt][2 * hf + 1] - mnew);
                s[nt][2 * hf] = p0; s[nt][2 * hf + 1] = p1;
                sum += p0 + p1;
                o[nt][2 * hf] *= alpha; o[nt][2 * hf + 1] *= alpha;
            }
            sum += __shfl_xor_sync(0xffffffffu, sum, 1);
            sum += __shfl_xor_sync(0xffffffffu, sum, 2);
            lrow[hf] = lrow[hf] * alpha + sum;
        }

        // ---- O += P @ V ----
        #pragma unroll
        for (int kt = 0; kt < 4; kt++) {
            uint32_t aPh[4], aPl[4];
            split_pair(s[2 * kt][0],     s[2 * kt][1],     aPh[0], aPl[0]);
            split_pair(s[2 * kt][2],     s[2 * kt][3],     aPh[1], aPl[1]);
            split_pair(s[2 * kt + 1][0], s[2 * kt + 1][1], aPh[2], aPl[2]);
            split_pair(s[2 * kt + 1][2], s[2 * kt + 1][3], aPh[3], aPl[3]);
            #pragma unroll
            for (int no = 0; no < 4; no++) {
                uint32_t tv[4];
                uint32_t ad = sVh + (kt * 16 + krow_v) * AT_PITCH + (no * 16 + ncol_v) * 2;
                ldm4t(tv, ad);
                mma16816(o[2 * no],     aPh, tv);
                mma16816(o[2 * no],     aPl, tv);
                mma16816(o[2 * no + 1], aPh, tv + 2);
                mma16816(o[2 * no + 1], aPl, tv + 2);
                ldm4t(tv, ad + AT_TILE);
                mma16816(o[2 * no],     aPh, tv);
                mma16816(o[2 * no + 1], aPh, tv + 2);
            }
        }
    }

    // ---- normalize + split-bf16 output ----
    #pragma unroll
    for (int hf = 0; hf < 2; hf++) {
        float inv = 1.f / lrow[hf];
        int r = qb * 128 + (w << 4) + (lane >> 2) + hf * 8;
        size_t base = (size_t)(b * TSEQ + r) * DIM + hh * HD;
        #pragma unroll
        for (int nt = 0; nt < 8; nt++) {
            int c = nt * 8 + (lane & 3) * 2;
            float v0 = o[nt][2 * hf] * inv, v1 = o[nt][2 * hf + 1] * inv;
            __nv_bfloat16 h0, l0, h1, l1;
            split_bf16(v0, h0, l0);
            split_bf16(v1, h1, l1);
            *(__nv_bfloat162*)&oh[base + c] = __nv_bfloat162(h0, h1);
            *(__nv_bfloat162*)&ol[base + c] = __nv_bfloat162(l0, l1);
        }
    }
}

// ---------------- last-layer out-proj: only last token per batch -----------
__global__ __launch_bounds__(128)
void outproj_last_kernel(const __nv_bfloat16* __restrict__ ah,
                         const __nv_bfloat16* __restrict__ al,
                         const float* __restrict__ wv,
                         const float* __restrict__ bias,
                         float* __restrict__ h) {
    __shared__ float x[DIM];
    const int b = blockIdx.y;
    const size_t row = (size_t)b * TSEQ + TSEQ - 1;
    for (int i = threadIdx.x; i < DIM; i += 128)
        x[i] = __bfloat162float(ah[row * DIM + i]) + __bfloat162float(al[row * DIM + i]);
    __syncthreads();
    const int n = blockIdx.x * 128 + threadIdx.x;
    float acc = bias[n];
    #pragma unroll 8
    for (int k = 0; k < DIM; k++)
        acc += x[k] * wv[(size_t)k * DIM + n];
    h[row * DIM + n] += acc;
}

// ---------------- LM head: split-D partials + deterministic reduce ---------
__global__ __launch_bounds__(256)
void head_part_kernel(const float* __restrict__ hlast, const float* __restrict__ hw,
                      float* __restrict__ part) {
    __shared__ float sh[2 * (DIM / DSPLIT)];
    const int d0 = blockIdx.y * (DIM / DSPLIT);
    if (threadIdx.x < DIM / DSPLIT) {
        sh[threadIdx.x]               = hlast[d0 + threadIdx.x];
        sh[DIM / DSPLIT + threadIdx.x] = hlast[DIM + d0 + threadIdx.x];
    }
    __syncthreads();
    int v = blockIdx.x * 256 + threadIdx.x;
    float a0 = 0.f, a1 = 0.f;
    #pragma unroll 8
    for (int d = 0; d < DIM / DSPLIT; d++) {
        float w = hw[(size_t)(d0 + d) * VOCAB + v];
        a0 += sh[d] * w;
        a1 += sh[DIM / DSPLIT + d] * w;
    }
    part[(size_t)(blockIdx.y * 2 + 0) * VOCAB + v] = a0;
    part[(size_t)(blockIdx.y * 2 + 1) * VOCAB + v] = a1;
}

__global__ __launch_bounds__(256)
void head_reduce_kernel(const float* __restrict__ part, const float* __restrict__ hb,
                        float* __restrict__ out) {
    int v = blockIdx.x * 256 + threadIdx.x;
    float b = hb[v];
    float a0 = b, a1 = b;
    #pragma unroll
    for (int j = 0; j < DSPLIT; j++) {
        a0 += part[(size_t)(j * 2 + 0) * VOCAB + v];
        a1 += part[(size_t)(j * 2 + 1) * VOCAB + v];
    }
    out[v]         = a0;
    out[VOCAB + v] = a1;
}

// ---------------- launch ----------------------------------------------------
extern "C" void kernel_launch(void* const* d_in, const int* in_sizes, int n_in,
                              void* d_out, int out_size) {
    const int*   tokens    = (const int*)  d_in[0];
    const float* tok_embed = (const float*)d_in[1];
    const float* pos_embed = (const float*)d_in[2];
    const float* qkv_w     = (const float*)d_in[3];
    const float* qkv_b     = (const float*)d_in[4];
    const float* out_w     = (const float*)d_in[5];
    const float* out_b     = (const float*)d_in[6];
    const float* ln_w      = (const float*)d_in[7];
    const float* ln_b      = (const float*)d_in[8];
    const float* lnf_w     = (const float*)d_in[9];
    const float* lnf_b     = (const float*)d_in[10];
    const float* head_w    = (const float*)d_in[11];
    const float* head_b    = (const float*)d_in[12];
    float* logits = (float*)d_out;

    float *ph, *pqkv, *phl, *ppart;
    __nv_bfloat16 *pxh, *pxl, *pah, *pal, *pwqh, *pwql, *pwoh, *pwol;
    cudaGetSymbolAddress((void**)&ph,    g_h);
    cudaGetSymbolAddress((void**)&pqkv,  g_qkv);
    cudaGetSymbolAddress((void**)&phl,   g_hl);
    cudaGetSymbolAddress((void**)&ppart, g_part);
    cudaGetSymbolAddress((void**)&pxh,   g_xh);
    cudaGetSymbolAddress((void**)&pxl,   g_xl);
    cudaGetSymbolAddress((void**)&pah,   g_ah);
    cudaGetSymbolAddress((void**)&pal,   g_al);
    cudaGetSymbolAddress((void**)&pwqh,  g_wqh);
    cudaGetSymbolAddress((void**)&pwql,  g_wql);
    cudaGetSymbolAddress((void**)&pwoh,  g_woh);
    cudaGetSymbolAddress((void**)&pwol,  g_wol);

    cudaFuncSetAttribute(attn_mma_kernel, cudaFuncAttributeMaxDynamicSharedMemorySize, ATTN_SMEM);
    cudaFuncSetAttribute(mma_gemm<false, false>, cudaFuncAttributeMaxDynamicSharedMemorySize, GEMM_SMEM);
    cudaFuncSetAttribute(mma_gemm<false, true>,  cudaFuncAttributeMaxDynamicSharedMemorySize, GEMM_SMEM);
    cudaFuncSetAttribute(mma_gemm<true, false>,  cudaFuncAttributeMaxDynamicSharedMemorySize, GEMM_SMEM);

    const int M = BATCH * TSEQ;
    const int NQB = TSEQ / 128;   // 8 query tiles of 128

    embed_kernel<<<M, 256>>>(tokens, tok_embed, pos_embed, ph);

    // streaming split (original layout, no transpose)
    wsplit_kernel<<<2368, 256>>>(qkv_w, pwqh, pwql, (size_t)NL * DIM * 3 * DIM);
    wsplit_kernel<<<2368, 256>>>(out_w, pwoh, pwol, (size_t)NL * DIM * DIM);

    for (int l = 0; l < NL; l++) {
        const bool last = (l == NL - 1);
        ln_split_kernel<<<M, 256>>>(ph, ln_w + (size_t)l * DIM, ln_b + (size_t)l * DIM, pxh, pxl);
        if (!last)
            mma_gemm<false, false><<<dim3(3 * DIM / BN, M / BM), 256, GEMM_SMEM>>>(
                pxh, pxl,
                pwqh + (size_t)l * DIM * 3 * DIM, pwql + (size_t)l * DIM * 3 * DIM,
                qkv_b + (size_t)l * 3 * DIM, pqkv, M, 3 * DIM);
        else
            mma_gemm<false, true><<<dim3(3 * DIM / BN, M / BM), 256, GEMM_SMEM>>>(
                pxh, pxl,
                pwqh + (size_t)l * DIM * 3 * DIM, pwql + (size_t)l * DIM * 3 * DIM,
                qkv_b + (size_t)l * 3 * DIM, pqkv, M, 3 * DIM);

        attn_mma_kernel<<<dim3(last ? 1 : NQB, NH, BATCH), 256, ATTN_SMEM>>>(
            pqkv, pah, pal, NQB - 1);

        if (!last)
            mma_gemm<true, false><<<dim3(DIM / BN, M / BM), 256, GEMM_SMEM>>>(
                pah, pal,
                pwoh + (size_t)l * DIM * DIM, pwol + (size_t)l * DIM * DIM,
                out_b + (size_t)l * DIM, ph, M, DIM);
        else
            outproj_last_kernel<<<dim3(DIM / 128, BATCH), 128>>>(
                pah, pal, out_w + (size_t)l * DIM * DIM, out_b + (size_t)l * DIM, ph);
    }

    lnf_kernel<<<BATCH, 256>>>(ph, lnf_w, lnf_b, phl);
    head_part_kernel<<<dim3(VOCAB / 256, DSPLIT), 256>>>(phl, head_w, ppart);
    head_reduce_kernel<<<VOCAB / 256, 256>>>(ppart, head_b, logits);
}

// round 13
// speedup vs baseline: 1.1105x; 1.1105x over previous
#include <cuda_runtime.h>
#include <cuda_bf16.h>
#include <math.h>
#include <stdint.h>

#define BATCH 2
#define TSEQ  1024
#define DIM   1024
#define NH    16
#define HD    64
#define NL    6
#define VOCAB 32000

// GEMM tiling (mma.sync path — portable to compute_103 virtual arch)
#define BM 128
#define BN 128
#define BK 64
#define PITCH_A     144                   // A smem row: 64 halfs + pad
#define A_BYTES     (128 * PITCH_A)       // 18432
#define PITCH_BB    272                   // B smem row: 128 halfs + pad ([k][n] layout)
#define B_BYTES     (64 * PITCH_BB)       // 17408
#define STAGE_BYTES (2 * A_BYTES + 2 * B_BYTES)   // 71680
#define GEMM_STAGES 3
#define GEMM_SMEM   (GEMM_STAGES * STAGE_BYTES)   // 215040

// attention tiling (R11-verified: BQ=64, single-buffer, 4 CTAs/SM)
#define AT_PITCH 144
#define AT_TILE  (64 * AT_PITCH)           // 9216 B per 64x64 bf16 tile
#define ATTN_SMEM (6 * AT_TILE)            // 55296 B

// head split
#define DSPLIT 8

// ---------------- scratch (device globals; no allocation allowed) ----------
__device__ float g_h   [BATCH * TSEQ * DIM];
__device__ float g_qkv [BATCH * TSEQ * 3 * DIM];
__device__ float g_hl  [BATCH * DIM];
__device__ float g_part[2 * DSPLIT * VOCAB];

__device__ __nv_bfloat16 g_xh[BATCH * TSEQ * DIM];
__device__ __nv_bfloat16 g_xl[BATCH * TSEQ * DIM];
__device__ __nv_bfloat16 g_ah[BATCH * TSEQ * DIM];
__device__ __nv_bfloat16 g_al[BATCH * TSEQ * DIM];

// weights split to bf16 hi/lo, kept in ORIGINAL (L, K, N) layout
__device__ __nv_bfloat16 g_wqh[NL * DIM * 3 * DIM];
__device__ __nv_bfloat16 g_wql[NL * DIM * 3 * DIM];
__device__ __nv_bfloat16 g_woh[NL * DIM * DIM];
__device__ __nv_bfloat16 g_wol[NL * DIM * DIM];

// ==================== helpers ====================
__device__ __forceinline__ uint32_t smem_u32(const void* p) {
    uint32_t a;
    asm("{ .reg .u64 t; cvta.to.shared.u64 t, %1; cvt.u32.u64 %0, t; }" : "=r"(a) : "l"(p));
    return a;
}
__device__ __forceinline__ void cp16(uint32_t d, const void* g) {
    asm volatile("cp.async.cg.shared.global [%0], [%1], 16;" :: "r"(d), "l"(g));
}
__device__ __forceinline__ void cp_commit() {
    asm volatile("cp.async.commit_group;");
}
__device__ __forceinline__ void ldm4(uint32_t* r, uint32_t addr) {
    asm volatile("ldmatrix.sync.aligned.m8n8.x4.shared.b16 {%0,%1,%2,%3}, [%4];"
        : "=r"(r[0]), "=r"(r[1]), "=r"(r[2]), "=r"(r[3]) : "r"(addr));
}
__device__ __forceinline__ void ldm4t(uint32_t* r, uint32_t addr) {
    asm volatile("ldmatrix.sync.aligned.m8n8.x4.trans.shared.b16 {%0,%1,%2,%3}, [%4];"
        : "=r"(r[0]), "=r"(r[1]), "=r"(r[2]), "=r"(r[3]) : "r"(addr));
}
__device__ __forceinline__ void mma16816(float* c, const uint32_t* a, const uint32_t* b) {
    asm volatile("mma.sync.aligned.m16n8k16.row.col.f32.bf16.bf16.f32 "
        "{%0,%1,%2,%3}, {%4,%5,%6,%7}, {%8,%9}, {%0,%1,%2,%3};"
        : "+f"(c[0]), "+f"(c[1]), "+f"(c[2]), "+f"(c[3])
        : "r"(a[0]), "r"(a[1]), "r"(a[2]), "r"(a[3]), "r"(b[0]), "r"(b[1]));
}
__device__ __forceinline__ uint32_t packbf(float lo, float hi) {
    uint32_t r;
    asm("cvt.rn.bf16x2.f32 %0, %1, %2;" : "=r"(r) : "f"(hi), "f"(lo));
    return r;
}
// pack (a,b) into hi-word pair + residual lo-word pair (a = element 0 = low half)
__device__ __forceinline__ void split_pair(float a, float b, uint32_t& hi, uint32_t& lo) {
    float ha = __bfloat162float(__float2bfloat16(a));
    float hb = __bfloat162float(__float2bfloat16(b));
    hi = packbf(a, b);
    lo = packbf(a - ha, b - hb);
}
__device__ __forceinline__ void split_bf16(float v, __nv_bfloat16& h, __nv_bfloat16& l) {
    h = __float2bfloat16(v);
    l = __float2bfloat16(v - __bfloat162float(h));
}

// ---------------- block reduce ---------------------------------------------
__device__ __forceinline__ float block_reduce_sum(float v, float* red) {
    #pragma unroll
    for (int o = 16; o > 0; o >>= 1) v += __shfl_down_sync(0xffffffffu, v, o);
    int w = threadIdx.x >> 5;
    if ((threadIdx.x & 31) == 0) red[w] = v;
    __syncthreads();
    if (threadIdx.x == 0) {
        float s = 0.f;
        #pragma unroll
        for (int i = 0; i < 8; i++) s += red[i];
        red[8] = s;
    }
    __syncthreads();
    float r = red[8];
    __syncthreads();
    return r;
}

// ---------------- fused embedding + layer-0 LN-split -----------------------
__global__ void embed_ln_kernel(const int* __restrict__ tokens,
                                const float* __restrict__ te,
                                const float* __restrict__ pe,
                                const float* __restrict__ w,
                                const float* __restrict__ bvec,
                                float* __restrict__ h,
                                __nv_bfloat16* __restrict__ xh,
                                __nv_bfloat16* __restrict__ xl) {
    __shared__ float red[9];
    const int m = blockIdx.x;
    const int t = m & (TSEQ - 1);
    const int tok = tokens[m];
    float v[4];
    #pragma unroll
    for (int i = 0; i < 4; i++) {
        int d = threadIdx.x + i * 256;
        v[i] = te[(size_t)tok * DIM + d] + pe[(size_t)t * DIM + d];
        h[(size_t)m * DIM + d] = v[i];
    }
    float mean = block_reduce_sum(v[0] + v[1] + v[2] + v[3], red) * (1.f / DIM);
    float d2 = 0.f;
    #pragma unroll
    for (int i = 0; i < 4; i++) { float tt = v[i] - mean; d2 += tt * tt; }
    float var = block_reduce_sum(d2, red) * (1.f / DIM);
    float inv = rsqrtf(var + 1e-5f);
    #pragma unroll
    for (int i = 0; i < 4; i++) {
        int d = threadIdx.x + i * 256;
        float y = (v[i] - mean) * inv * w[d] + bvec[d];
        __nv_bfloat16 hh, ll;
        split_bf16(y, hh, ll);
        xh[(size_t)m * DIM + d] = hh;
        xl[(size_t)m * DIM + d] = ll;
    }
}

// ---------------- streaming fp32->bf16 split (no transpose) ----------------
__global__ void wsplit_kernel(const float* __restrict__ W,
                              __nv_bfloat16* __restrict__ Th,
                              __nv_bfloat16* __restrict__ Tl,
                              size_t n) {
    size_t i = ((size_t)blockIdx.x * blockDim.x + threadIdx.x) * 8;
    size_t stride = (size_t)gridDim.x * blockDim.x * 8;
    for (; i < n; i += stride) {
        float4 v0 = *(const float4*)(W + i);
        float4 v1 = *(const float4*)(W + i + 4);
        uint32_t h0, l0, h1, l1, h2, l2, h3, l3;
        split_pair(v0.x, v0.y, h0, l0);
        split_pair(v0.z, v0.w, h1, l1);
        split_pair(v1.x, v1.y, h2, l2);
        split_pair(v1.z, v1.w, h3, l3);
        *(uint4*)(Th + i) = make_uint4(h0, h1, h2, h3);
        *(uint4*)(Tl + i) = make_uint4(l0, l1, l2, l3);
    }
}

// ---------------- layernorm -> split bf16 ----------------------------------
__global__ void ln_split_kernel(const float* __restrict__ src,
                                const float* __restrict__ w,
                                const float* __restrict__ bvec,
                                __nv_bfloat16* __restrict__ xh,
                                __nv_bfloat16* __restrict__ xl) {
    __shared__ float red[9];
    const int rowi = blockIdx.x;
    const float* x = src + (size_t)rowi * DIM;
    float v[4];
    #pragma unroll
    for (int i = 0; i < 4; i++) v[i] = x[threadIdx.x + i * 256];
    float mean = block_reduce_sum(v[0] + v[1] + v[2] + v[3], red) * (1.f / DIM);
    float d2 = 0.f;
    #pragma unroll
    for (int i = 0; i < 4; i++) { float t = v[i] - mean; d2 += t * t; }
    float var = block_reduce_sum(d2, red) * (1.f / DIM);
    float inv = rsqrtf(var + 1e-5f);
    #pragma unroll
    for (int i = 0; i < 4; i++) {
        int d = threadIdx.x + i * 256;
        float y = (v[i] - mean) * inv * w[d] + bvec[d];
        __nv_bfloat16 hh, ll;
        split_bf16(y, hh, ll);
        xh[(size_t)rowi * DIM + d] = hh;
        xl[(size_t)rowi * DIM + d] = ll;
    }
}

// final layernorm, only last token, fp32 out
__global__ void lnf_kernel(const float* __restrict__ src,
                           const float* __restrict__ w,
                           const float* __restrict__ bvec,
                           float* __restrict__ dst) {
    __shared__ float red[9];
    const int rowi = blockIdx.x * TSEQ + (TSEQ - 1);
    const float* x = src + (size_t)rowi * DIM;
    float v[4];
    #pragma unroll
    for (int i = 0; i < 4; i++) v[i] = x[threadIdx.x + i * 256];
    float mean = block_reduce_sum(v[0] + v[1] + v[2] + v[3], red) * (1.f / DIM);
    float d2 = 0.f;
    #pragma unroll
    for (int i = 0; i < 4; i++) { float t = v[i] - mean; d2 += t * t; }
    float var = block_reduce_sum(d2, red) * (1.f / DIM);
    float inv = rsqrtf(var + 1e-5f);
    #pragma unroll
    for (int i = 0; i < 4; i++) {
        int d = threadIdx.x + i * 256;
        dst[(size_t)blockIdx.x * DIM + d] = (v[i] - mean) * inv * w[d] + bvec[d];
    }
}

// ---------------- HMMA split-bf16 GEMM (B in native [K,N] layout) ----------
// SKIPQ: last-layer QKV — skip Q-column tiles except M-tiles holding last tokens.
template <bool RESID, bool SKIPQ>
__global__ __launch_bounds__(256, 1)
void mma_gemm(const __nv_bfloat16* __restrict__ Ah, const __nv_bfloat16* __restrict__ Al,
              const __nv_bfloat16* __restrict__ Bh, const __nv_bfloat16* __restrict__ Bl,
              const float* __restrict__ bias, float* __restrict__ C,
              int M, int N) {
    const int row0 = blockIdx.y * BM;
    const int col0 = blockIdx.x * BN;
    if (SKIPQ && col0 < DIM && (blockIdx.y & 7) != 7) return;

    extern __shared__ char smem[];
    const uint32_t sbase = smem_u32(smem);
    const int tid  = threadIdx.x;
    const int lane = tid & 31;
    const int wid  = tid >> 5;
    const int wm   = wid >> 1;
    const int wn   = wid & 1;
    const int K    = DIM;
    const int NC   = K / BK;              // 16

    float acc[2][8][4];
    #pragma unroll
    for (int i = 0; i < 2; i++)
        #pragma unroll
        for (int j = 0; j < 8; j++)
            #pragma unroll
            for (int q = 0; q < 4; q++) acc[i][j][q] = 0.f;

    auto load_stage = [&](int s, int c) {
        const uint32_t sb = sbase + s * STAGE_BYTES;
        const int kt = c * BK;
        #pragma unroll
        for (int it = 0; it < 4; it++) {
            int lin = tid + it * 256;
            int r  = lin >> 3;
            int cq = lin & 7;
            size_t go = (size_t)(row0 + r) * K + kt + cq * 8;
            uint32_t d = sb + r * PITCH_A + cq * 16;
            cp16(d, Ah + go);
            cp16(d + A_BYTES, Al + go);
        }
        #pragma unroll
        for (int it = 0; it < 4; it++) {
            int lin = tid + it * 256;
            int r  = lin >> 4;
            int cq = lin & 15;
            size_t go = (size_t)(kt + r) * N + col0 + cq * 8;
            uint32_t d = sb + 2 * A_BYTES + r * PITCH_BB + cq * 16;
            cp16(d, Bh + go);
            cp16(d + B_BYTES, Bl + go);
        }
    };

    load_stage(0, 0); cp_commit();
    load_stage(1, 1); cp_commit();
    load_stage(2, 2); cp_commit();

    const int arow  = wm * 32 + (lane & 15);
    const int acol8 = (lane >> 4) << 3;
    const int krow_b = (lane & 7) + ((lane >> 3) & 1) * 8;
    const int ncol_b = (lane >> 4) << 3;

    int stage = 0;
    for (int c = 0; c < NC; c++) {
        if (c + 3 <= NC)      asm volatile("cp.async.wait_group 2;");
        else if (c + 2 == NC) asm volatile("cp.async.wait_group 1;");
        else                  asm volatile("cp.async.wait_group 0;");
        __syncthreads();

        const uint32_t ab = sbase + stage * STAGE_BYTES;
        const uint32_t bb = ab + 2 * A_BYTES;
        #pragma unroll
        for (int ks = 0; ks < 4; ks++) {
            const int kc = ks * 16;
            uint32_t ah[2][4], al[2][4];
            #pragma unroll
            for (int mt = 0; mt < 2; mt++) {
                uint32_t ad = ab + (uint32_t)(arow + mt * 16) * PITCH_A + (uint32_t)(kc + acol8) * 2;
                ldm4(ah[mt], ad);
                ldm4(al[mt], ad + A_BYTES);
            }
            uint32_t bh[8][2], bl[8][2];
            #pragma unroll
            for (int ng = 0; ng < 4; ng++) {
                uint32_t bd = bb + (uint32_t)(kc + krow_b) * PITCH_BB
                                 + (uint32_t)(wn * 64 + ng * 16 + ncol_b) * 2;
                uint32_t t4[4];
                ldm4t(t4, bd);
                bh[ng * 2][0] = t4[0]; bh[ng * 2][1] = t4[1];
                bh[ng * 2 + 1][0] = t4[2]; bh[ng * 2 + 1][1] = t4[3];
                ldm4t(t4, bd + B_BYTES);
                bl[ng * 2][0] = t4[0]; bl[ng * 2][1] = t4[1];
                bl[ng * 2 + 1][0] = t4[2]; bl[ng * 2 + 1][1] = t4[3];
            }
            #pragma unroll
            for (int mt = 0; mt < 2; mt++)
                #pragma unroll
                for (int nt = 0; nt < 8; nt++) {
                    mma16816(acc[mt][nt], ah[mt], bh[nt]);
                    mma16816(acc[mt][nt], ah[mt], bl[nt]);
                    mma16816(acc[mt][nt], al[mt], bh[nt]);
                }
        }
        __syncthreads();
        if (c + 3 < NC) { load_stage(stage, c + 3); cp_commit(); }
        stage = (stage == 2) ? 0 : stage + 1;
    }

    #pragma unroll
    for (int mt = 0; mt < 2; mt++) {
        #pragma unroll
        for (int nt = 0; nt < 8; nt++) {
            int r  = row0 + wm * 32 + mt * 16 + (lane >> 2);
            int cc = col0 + wn * 64 + nt * 8 + (lane & 3) * 2;
            float b0 = bias[cc], b1 = bias[cc + 1];
            float2* p0 = (float2*)&C[(size_t)r * N + cc];
            float2* p1 = (float2*)&C[(size_t)(r + 8) * N + cc];
            float2 v0 = make_float2(acc[mt][nt][0] + b0, acc[mt][nt][1] + b1);
            float2 v1 = make_float2(acc[mt][nt][2] + b0, acc[mt][nt][3] + b1);
            if (RESID) {
                float2 o0 = *p0, o1 = *p1;
                v0.x += o0.x; v0.y += o0.y;
                v1.x += o1.x; v1.y += o1.y;
            }
            *p0 = v0;
            *p1 = v1;
        }
    }
}

// ---------------- HMMA causal flash attention (R11 config) -----------------
__global__ __launch_bounds__(128)
void attn_mma_kernel(const float* __restrict__ qkv,
                     __nv_bfloat16* __restrict__ oh,
                     __nv_bfloat16* __restrict__ ol,
                     int qb0) {
    extern __shared__ char asmem[];
    const uint32_t sb = smem_u32(asmem);
    const uint32_t sQh = sb;
    const uint32_t sKh = sb + 2 * AT_TILE;
    const uint32_t sVh = sb + 4 * AT_TILE;
    const int tid = threadIdx.x, lane = tid & 31, w = tid >> 5;
    const int qb = qb0 - (int)blockIdx.x;   // heavy blocks first
    const int hh = blockIdx.y, b = blockIdx.z;

    #pragma unroll
    for (int i = 0; i < 8; i++) {
        int lin = tid + i * 128, r = lin >> 4, c4 = lin & 15;
        float4 q = *(const float4*)&qkv[(size_t)(b * TSEQ + qb * 64 + r) * (3 * DIM) + hh * HD + c4 * 4];
        q.x *= 0.125f; q.y *= 0.125f; q.z *= 0.125f; q.w *= 0.125f;
        uint32_t h0, l0, h1, l1;
        split_pair(q.x, q.y, h0, l0);
        split_pair(q.z, q.w, h1, l1);
        int off = r * AT_PITCH + c4 * 8;
        *(uint2*)(asmem + off)           = make_uint2(h0, h1);
        *(uint2*)(asmem + AT_TILE + off) = make_uint2(l0, l1);
    }
    __syncthreads();

    uint32_t qh[4][4], ql[4][4];
    {
        int r  = (w << 4) + (lane & 15);
        int c8 = (lane >> 4) << 3;
        #pragma unroll
        for (int kc = 0; kc < 4; kc++) {
            uint32_t ad = sQh + (uint32_t)r * AT_PITCH + (uint32_t)(kc * 16 + c8) * 2;
            ldm4(qh[kc], ad);
            ldm4(ql[kc], ad + AT_TILE);
        }
    }

    float o[8][4];
    #pragma unroll
    for (int nt = 0; nt < 8; nt++)
        #pragma unroll
        for (int q = 0; q < 4; q++) o[nt][q] = 0.f;
    float mrow[2] = {-1e30f, -1e30f};
    float lrow[2] = {0.f, 0.f};

    const uint32_t krow_s = (uint32_t)((lane & 7) + ((lane >> 4) << 3));
    const uint32_t kcol_s = (uint32_t)(((lane >> 3) & 1) << 3);
    const uint32_t krow_v = (uint32_t)((lane & 7) + (((lane >> 3) & 1) << 3));
    const uint32_t ncol_v = (uint32_t)((lane >> 4) << 3);

    for (int kb = 0; kb <= qb; kb++) {
        __syncthreads();
        #pragma unroll
        for (int i = 0; i < 8; i++) {
            int lin = tid + i * 128, r = lin >> 4, c4 = lin & 15;
            size_t gb = (size_t)(b * TSEQ + kb * 64 + r) * (3 * DIM) + DIM + hh * HD + c4 * 4;
            float4 kv = *(const float4*)&qkv[gb];
            float4 vv = *(const float4*)&qkv[gb + DIM];
            uint32_t h0, l0, h1, l1;
            int off = r * AT_PITCH + c4 * 8;
            split_pair(kv.x, kv.y, h0, l0);
            split_pair(kv.z, kv.w, h1, l1);
            *(uint2*)(asmem + 2 * AT_TILE + off) = make_uint2(h0, h1);
            *(uint2*)(asmem + 3 * AT_TILE + off) = make_uint2(l0, l1);
            split_pair(vv.x, vv.y, h0, l0);
            split_pair(vv.z, vv.w, h1, l1);
            *(uint2*)(asmem + 4 * AT_TILE + off) = make_uint2(h0, h1);
            *(uint2*)(asmem + 5 * AT_TILE + off) = make_uint2(l0, l1);
        }
        __syncthreads();

        float s[8][4];
        #pragma unroll
        for (int nt = 0; nt < 8; nt++)
            #pragma unroll
            for (int q = 0; q < 4; q++) s[nt][q] = 0.f;
        #pragma unroll
        for (int kc = 0; kc < 4; kc++) {
            #pragma unroll
            for (int ng = 0; ng < 4; ng++) {
                uint32_t th[4], tl[4];
                uint32_t ad = sKh + (ng * 16 + krow_s) * AT_PITCH + (kc * 16 + kcol_s) * 2;
                ldm4(th, ad);
                ldm4(tl, ad + AT_TILE);
                mma16816(s[2 * ng],     qh[kc], th);
                mma16816(s[2 * ng],     ql[kc], th);
                mma16816(s[2 * ng],     qh[kc], tl);
                mma16816(s[2 * ng + 1], qh[kc], th + 2);
                mma16816(s[2 * ng + 1], ql[kc], th + 2);
                mma16816(s[2 * ng + 1], qh[kc], tl + 2);
            }
        }

        if (kb == qb) {
            int rl = (w << 4) + (lane >> 2);
            #pragma unroll
            for (int nt = 0; nt < 8; nt++) {
                int cl = nt * 8 + (lane & 3) * 2;
                if (cl     > rl)     s[nt][0] = -1e30f;
                if (cl + 1 > rl)     s[nt][1] = -1e30f;
                if (cl     > rl + 8) s[nt][2] = -1e30f;
                if (cl + 1 > rl + 8) s[nt][3] = -1e30f;
            }
        }

        #pragma unroll
        for (int hf = 0; hf < 2; hf++) {
            float mx = -1e30f;
            #pragma unroll
            for (int nt = 0; nt < 8; nt++)
                mx = fmaxf(mx, fmaxf(s[nt][2 * hf], s[nt][2 * hf + 1]));
            mx = fmaxf(mx, __shfl_xor_sync(0xffffffffu, mx, 1));
            mx = fmaxf(mx, __shfl_xor_sync(0xffffffffu, mx, 2));
            float mnew  = fmaxf(mrow[hf], mx);
            float alpha = __expf(mrow[hf] - mnew);
            mrow[hf] = mnew;
            float sum = 0.f;
            #pragma unroll
            for (int nt = 0; nt < 8; nt++) {
                float p0 = __expf(s[nt][2 * hf]     - mnew);
                float p1 = __expf(s[nt][2 * hf + 1] - mnew);
                s[nt][2 * hf] = p0; s[nt][2 * hf + 1] = p1;
                sum += p0 + p1;
                o[nt][2 * hf] *= alpha; o[nt][2 * hf + 1] *= alpha;
            }
            sum += __shfl_xor_sync(0xffffffffu, sum, 1);
            sum += __shfl_xor_sync(0xffffffffu, sum, 2);
            lrow[hf] = lrow[hf] * alpha + sum;
        }

        #pragma unroll
        for (int kt = 0; kt < 4; kt++) {
            uint32_t aPh[4], aPl[4];
            split_pair(s[2 * kt][0],     s[2 * kt][1],     aPh[0], aPl[0]);
            split_pair(s[2 * kt][2],     s[2 * kt][3],     aPh[1], aPl[1]);
            split_pair(s[2 * kt + 1][0], s[2 * kt + 1][1], aPh[2], aPl[2]);
            split_pair(s[2 * kt + 1][2], s[2 * kt + 1][3], aPh[3], aPl[3]);
            #pragma unroll
            for (int no = 0; no < 4; no++) {
                uint32_t tv[4];
                uint32_t ad = sVh + (kt * 16 + krow_v) * AT_PITCH + (no * 16 + ncol_v) * 2;
                ldm4t(tv, ad);
                mma16816(o[2 * no],     aPh, tv);
                mma16816(o[2 * no],     aPl, tv);
                mma16816(o[2 * no + 1], aPh, tv + 2);
                mma16816(o[2 * no + 1], aPl, tv + 2);
                ldm4t(tv, ad + AT_TILE);
                mma16816(o[2 * no],     aPh, tv);
                mma16816(o[2 * no + 1], aPh, tv + 2);
            }
        }
    }

    #pragma unroll
    for (int hf = 0; hf < 2; hf++) {
        float inv = 1.f / lrow[hf];
        int r = qb * 64 + (w << 4) + (lane >> 2) + hf * 8;
        size_t base = (size_t)(b * TSEQ + r) * DIM + hh * HD;
        #pragma unroll
        for (int nt = 0; nt < 8; nt++) {
            int c = nt * 8 + (lane & 3) * 2;
            float v0 = o[nt][2 * hf] * inv, v1 = o[nt][2 * hf + 1] * inv;
            __nv_bfloat16 h0, l0, h1, l1;
            split_bf16(v0, h0, l0);
            split_bf16(v1, h1, l1);
            *(__nv_bfloat162*)&oh[base + c] = __nv_bfloat162(h0, h1);
            *(__nv_bfloat162*)&ol[base + c] = __nv_bfloat162(l0, l1);
        }
    }
}

// ---------------- last-layer out-proj: only last token per batch -----------
__global__ __launch_bounds__(128)
void outproj_last_kernel(const __nv_bfloat16* __restrict__ ah,
                         const __nv_bfloat16* __restrict__ al,
                         const float* __restrict__ wv,
                         const float* __restrict__ bias,
                         float* __restrict__ h) {
    __shared__ float x[DIM];
    const int b = blockIdx.y;
    const size_t row = (size_t)b * TSEQ + TSEQ - 1;
    for (int i = threadIdx.x; i < DIM; i += 128)
        x[i] = __bfloat162float(ah[row * DIM + i]) + __bfloat162float(al[row * DIM + i]);
    __syncthreads();
    const int n = blockIdx.x * 128 + threadIdx.x;
    float acc = bias[n];
    #pragma unroll 8
    for (int k = 0; k < DIM; k++)
        acc += x[k] * wv[(size_t)k * DIM + n];
    h[row * DIM + n] += acc;
}

// ---------------- LM head: split-D partials + deterministic reduce ---------
__global__ __launch_bounds__(256)
void head_part_kernel(const float* __restrict__ hlast, const float* __restrict__ hw,
                      float* __restrict__ part) {
    __shared__ float sh[2 * (DIM / DSPLIT)];
    const int d0 = blockIdx.y * (DIM / DSPLIT);
    if (threadIdx.x < DIM / DSPLIT) {
        sh[threadIdx.x]                = hlast[d0 + threadIdx.x];
        sh[DIM / DSPLIT + threadIdx.x] = hlast[DIM + d0 + threadIdx.x];
    }
    __syncthreads();
    int v = blockIdx.x * 256 + threadIdx.x;
    float a0 = 0.f, a1 = 0.f;
    #pragma unroll 8
    for (int d = 0; d < DIM / DSPLIT; d++) {
        float w = hw[(size_t)(d0 + d) * VOCAB + v];
        a0 += sh[d] * w;
        a1 += sh[DIM / DSPLIT + d] * w;
    }
    part[(size_t)(blockIdx.y * 2 + 0) * VOCAB + v] = a0;
    part[(size_t)(blockIdx.y * 2 + 1) * VOCAB + v] = a1;
}

__global__ __launch_bounds__(256)
void head_reduce_kernel(const float* __restrict__ part, const float* __restrict__ hb,
                        float* __restrict__ out) {
    int v = blockIdx.x * 256 + threadIdx.x;
    float b = hb[v];
    float a0 = b, a1 = b;
    #pragma unroll
    for (int j = 0; j < DSPLIT; j++) {
        a0 += part[(size_t)(j * 2 + 0) * VOCAB + v];
        a1 += part[(size_t)(j * 2 + 1) * VOCAB + v];
    }
    out[v]         = a0;
    out[VOCAB + v] = a1;
}

// ---------------- launch ----------------------------------------------------
extern "C" void kernel_launch(void* const* d_in, const int* in_sizes, int n_in,
                              void* d_out, int out_size) {
    const int*   tokens    = (const int*)  d_in[0];
    const float* tok_embed = (const float*)d_in[1];
    const float* pos_embed = (const float*)d_in[2];
    const float* qkv_w     = (const float*)d_in[3];
    const float* qkv_b     = (const float*)d_in[4];
    const float* out_w     = (const float*)d_in[5];
    const float* out_b     = (const float*)d_in[6];
    const float* ln_w      = (const float*)d_in[7];
    const float* ln_b      = (const float*)d_in[8];
    const float* lnf_w     = (const float*)d_in[9];
    const float* lnf_b     = (const float*)d_in[10];
    const float* head_w    = (const float*)d_in[11];
    const float* head_b    = (const float*)d_in[12];
    float* logits = (float*)d_out;

    float *ph, *pqkv, *phl, *ppart;
    __nv_bfloat16 *pxh, *pxl, *pah, *pal, *pwqh, *pwql, *pwoh, *pwol;
    cudaGetSymbolAddress((void**)&ph,    g_h);
    cudaGetSymbolAddress((void**)&pqkv,  g_qkv);
    cudaGetSymbolAddress((void**)&phl,   g_hl);
    cudaGetSymbolAddress((void**)&ppart, g_part);
    cudaGetSymbolAddress((void**)&pxh,   g_xh);
    cudaGetSymbolAddress((void**)&pxl,   g_xl);
    cudaGetSymbolAddress((void**)&pah,   g_ah);
    cudaGetSymbolAddress((void**)&pal,   g_al);
    cudaGetSymbolAddress((void**)&pwqh,  g_wqh);
    cudaGetSymbolAddress((void**)&pwql,  g_wql);
    cudaGetSymbolAddress((void**)&pwoh,  g_woh);
    cudaGetSymbolAddress((void**)&pwol,  g_wol);

    cudaFuncSetAttribute(attn_mma_kernel, cudaFuncAttributeMaxDynamicSharedMemorySize, ATTN_SMEM);
    cudaFuncSetAttribute(mma_gemm<false, false>, cudaFuncAttributeMaxDynamicSharedMemorySize, GEMM_SMEM);
    cudaFuncSetAttribute(mma_gemm<false, true>,  cudaFuncAttributeMaxDynamicSharedMemorySize, GEMM_SMEM);
    cudaFuncSetAttribute(mma_gemm<true, false>,  cudaFuncAttributeMaxDynamicSharedMemorySize, GEMM_SMEM);

    const int M = BATCH * TSEQ;
    const int NQB = TSEQ / 64;

    // fused embed + layer-0 LN
    embed_ln_kernel<<<M, 256>>>(tokens, tok_embed, pos_embed, ln_w, ln_b, ph, pxh, pxl);

    // streaming split (original layout, no transpose)
    wsplit_kernel<<<2368, 256>>>(qkv_w, pwqh, pwql, (size_t)NL * DIM * 3 * DIM);
    wsplit_kernel<<<2368, 256>>>(out_w, pwoh, pwol, (size_t)NL * DIM * DIM);

    for (int l = 0; l < NL; l++) {
        const bool last = (l == NL - 1);
        if (l > 0)
            ln_split_kernel<<<M, 256>>>(ph, ln_w + (size_t)l * DIM, ln_b + (size_t)l * DIM, pxh, pxl);
        if (!last)
            mma_gemm<false, false><<<dim3(3 * DIM / BN, M / BM), 256, GEMM_SMEM>>>(
                pxh, pxl,
                pwqh + (size_t)l * DIM * 3 * DIM, pwql + (size_t)l * DIM * 3 * DIM,
                qkv_b + (size_t)l * 3 * DIM, pqkv, M, 3 * DIM);
        else
            mma_gemm<false, true><<<dim3(3 * DIM / BN, M / BM), 256, GEMM_SMEM>>>(
                pxh, pxl,
                pwqh + (size_t)l * DIM * 3 * DIM, pwql + (size_t)l * DIM * 3 * DIM,
                qkv_b + (size_t)l * 3 * DIM, pqkv, M, 3 * DIM);

        attn_mma_kernel<<<dim3(last ? 1 : NQB, NH, BATCH), 128, ATTN_SMEM>>>(
            pqkv, pah, pal, NQB - 1);

        if (!last)
            mma_gemm<true, false><<<dim3(DIM / BN, M / BM), 256, GEMM_SMEM>>>(
                pah, pal,
                pwoh + (size_t)l * DIM * DIM, pwol + (size_t)l * DIM * DIM,
                out_b + (size_t)l * DIM, ph, M, DIM);
        else
            outproj_last_kernel<<<dim3(DIM / 128, BATCH), 128>>>(
                pah, pal, out_w + (size_t)l * DIM * DIM, out_b + (size_t)l * DIM, ph);
    }

    lnf_kernel<<<BATCH, 256>>>(ph, lnf_w, lnf_b, phl);
    head_part_kernel<<<dim3(VOCAB / 256, DSPLIT), 256>>>(phl, head_w, ppart);
    head_reduce_kernel<<<VOCAB / 256, 256>>>(ppart, head_b, logits);
}